// round 4
// baseline (speedup 1.0000x reference)
#include <cuda_runtime.h>
#include <math.h>

#define B_ 4
#define C_ 32
#define L_ 256
#define M_ 256
#define F_ 8
#define N_ 64
#define GRID_ 512          // 2 (b,l) per CTA, processed CONCURRENTLY -> single wave
#define CL_ (L_ * M_)      // c-stride in x

typedef unsigned long long u64;

__device__ __forceinline__ u64 ffma2(u64 a, u64 b, u64 c) {
    u64 d;
    asm("fma.rn.f32x2 %0, %1, %2, %3;" : "=l"(d) : "l"(a), "l"(b), "l"(c));
    return d;
}
__device__ __forceinline__ void upk(u64 v, float& x, float& y) {
    asm("mov.b64 {%0, %1}, %2;" : "=f"(x), "=f"(y) : "l"(v));
}
// Flip sign of both f32 lanes (2x LOP3 on the mostly idle ALU pipe).
__device__ __forceinline__ u64 neg2(u64 v) {
    u64 d;
    asm("{\n\t"
        ".reg .b32 lo, hi;\n\t"
        "mov.b64 {lo, hi}, %1;\n\t"
        "xor.b32 lo, lo, 0x80000000;\n\t"
        "xor.b32 hi, hi, 0x80000000;\n\t"
        "mov.b64 %0, {lo, hi};\n\t"
        "}" : "=l"(d) : "l"(v));
    return d;
}
// 16B global load as two u64.
__device__ __forceinline__ void ldg128(const float* p, u64& a, u64& b) {
    asm("ld.global.nc.v2.u64 {%0, %1}, [%2];" : "=l"(a), "=l"(b) : "l"(p));
}

__global__ __launch_bounds__(128, 4) void sphere_conv_kernel(
    const float* __restrict__ xr, const float* __restrict__ xi,
    const float* __restrict__ wr, const float* __restrict__ wi,
    float* __restrict__ out)
{
    // [group][c*F+f] : {wr, wr, wi, wi}, 16B each
    __shared__ float4 w4s[2][C_ * F_];

    const int tid   = threadIdx.x;
    const int group = tid >> 6;          // 0/1: which (b,l) this warp-pair works on
    const int t     = tid & 63;          // thread within group; owns m = 4*t .. 4*t+3

    // ---- fill both groups' interpolated weights (512 float4, 4 per thread) ----
    for (int i = tid; i < 2 * F_ * C_; i += 128) {
        const int g   = i >> 8;
        const int idx = i & 255;
        const int f   = idx & (F_ - 1);
        const int c   = idx >> 3;
        const int blg = blockIdx.x * 2 + g;
        const int lg  = blg & (L_ - 1);
        const float tt = (float)(lg * (N_ - 1)) * (1.0f / (float)(L_ - 1));
        int lo = (int)tt;
        if (lo > N_ - 2) lo = N_ - 2;
        const float frac = tt - (float)lo;
        const float om   = 1.0f - frac;
        const int wix = (f * C_ + c) * N_ + lo;     // w layout (F,C,N,1)
        const float wrv = wr[wix] * om + wr[wix + 1] * frac;
        const float wiv = wi[wix] * om + wi[wix + 1] * frac;
        w4s[g][c * F_ + f] = make_float4(wrv, wrv, wiv, wiv);
    }
    __syncthreads();

    const int bl = blockIdx.x * 2 + group;
    const int b  = bl >> 8;              // L_ == 256
    const int l  = bl & (L_ - 1);

    const unsigned int sbase =
        (unsigned int)__cvta_generic_to_shared(&w4s[group][0]);

    u64 pr[F_][2], pi[F_][2];
#pragma unroll
    for (int f = 0; f < F_; ++f) {
        pr[f][0] = pr[f][1] = 0ull;
        pi[f][0] = pi[f][1] = 0ull;
    }

    const int base = b * (C_ * CL_) + l * M_ + 4 * t;
    const float* xrp = xr + base;
    const float* xip = xi + base;

    // double-buffered c-PAIRS: buf[buf][c-in-pair][xr_lo,xr_hi,xi_lo,xi_hi]
    u64 buf[2][2][4];
#pragma unroll
    for (int j = 0; j < 2; ++j) {
        ldg128(xrp + j * CL_, buf[0][j][0], buf[0][j][1]);
        ldg128(xip + j * CL_, buf[0][j][2], buf[0][j][3]);
    }

    unsigned int soff = sbase;
#pragma unroll 2
    for (int cp = 0; cp < 16; ++cp) {
        const int cur = cp & 1, nxt = cur ^ 1;
        if (cp < 15) {
#pragma unroll
            for (int j = 0; j < 2; ++j) {
                const int c = (cp + 1) * 2 + j;
                ldg128(xrp + c * CL_, buf[nxt][j][0], buf[nxt][j][1]);
                ldg128(xip + c * CL_, buf[nxt][j][2], buf[nxt][j][3]);
            }
        }
#pragma unroll
        for (int j = 0; j < 2; ++j) {
            const u64 xr0 = buf[cur][j][0], xr1 = buf[cur][j][1];
            const u64 xi0 = buf[cur][j][2], xi1 = buf[cur][j][3];
            const u64 ni0 = neg2(xi0),      ni1 = neg2(xi1);
#pragma unroll
            for (int f = 0; f < F_; ++f) {
                u64 wrr, wii;
                asm("ld.shared.v2.u64 {%0, %1}, [%2];"
                    : "=l"(wrr), "=l"(wii)
                    : "r"(soff + (unsigned)(f * 16)));
                pr[f][0] = ffma2(wrr, xr0, pr[f][0]);
                pr[f][1] = ffma2(wrr, xr1, pr[f][1]);
                pr[f][0] = ffma2(wii, ni0, pr[f][0]);
                pr[f][1] = ffma2(wii, ni1, pr[f][1]);
                pi[f][0] = ffma2(wii, xr0, pi[f][0]);
                pi[f][1] = ffma2(wii, xr1, pi[f][1]);
                pi[f][0] = ffma2(wrr, xi0, pi[f][0]);
                pi[f][1] = ffma2(wrr, xi1, pi[f][1]);
            }
            soff += F_ * 16;             // next c
        }
    }

    // scale = sqrt(1+l)/C ; relu on real part only
    const float s  = sqrtf(1.0f + (float)l) * (1.0f / (float)C_);
    const int  m0  = 4 * t;
    float4* outp   = (float4*)out;
    const int ob   = (b * F_ * L_ + l) * M_ + m0;
#pragma unroll
    for (int f = 0; f < F_; ++f) {
        float r0, r1, r2, r3, i0, i1, i2, i3;
        upk(pr[f][0], r0, r1); upk(pr[f][1], r2, r3);
        upk(pi[f][0], i0, i1); upk(pi[f][1], i2, i3);
        const int idx = ob + f * (L_ * M_);
        outp[idx >> 2] = make_float4(fmaxf(r0 * s, 0.0f), fmaxf(r1 * s, 0.0f),
                                     fmaxf(r2 * s, 0.0f), fmaxf(r3 * s, 0.0f));
        outp[(idx + B_ * F_ * L_ * M_) >> 2] =
            make_float4(i0 * s, i1 * s, i2 * s, i3 * s);
    }
}

extern "C" void kernel_launch(void* const* d_in, const int* in_sizes, int n_in,
                              void* d_out, int out_size) {
    (void)in_sizes; (void)n_in; (void)out_size;
    sphere_conv_kernel<<<GRID_, 128>>>(
        (const float*)d_in[0], (const float*)d_in[1],
        (const float*)d_in[2], (const float*)d_in[3],
        (float*)d_out);
}

// round 7
// speedup vs baseline: 1.0115x; 1.0115x over previous
#include <cuda_runtime.h>
#include <math.h>

#define B_ 4
#define C_ 32
#define L_ 256
#define M_ 256
#define F_ 8
#define N_ 64
#define CL_ (L_ * M_)      // c-stride in x (elements)
#define STG_ 3             // pipeline stages
#define CPS_ 4             // c-rows per stage
#define SG_  (C_ / CPS_)   // 8 stage-groups
#define STGB_ (CPS_ * 2 * M_ * 4)   // bytes per stage = 8192

typedef unsigned long long u64;

__device__ __forceinline__ u64 ffma2(u64 a, u64 b, u64 c) {
    u64 d;
    asm("fma.rn.f32x2 %0, %1, %2, %3;" : "=l"(d) : "l"(a), "l"(b), "l"(c));
    return d;
}
__device__ __forceinline__ void upk(u64 v, float& x, float& y) {
    asm("mov.b64 {%0, %1}, %2;" : "=f"(x), "=f"(y) : "l"(v));
}
__device__ __forceinline__ u64 neg2(u64 v) {
    u64 d;
    asm("{\n\t"
        ".reg .b32 lo, hi;\n\t"
        "mov.b64 {lo, hi}, %1;\n\t"
        "xor.b32 lo, lo, 0x80000000;\n\t"
        "xor.b32 hi, hi, 0x80000000;\n\t"
        "mov.b64 %0, {lo, hi};\n\t"
        "}" : "=l"(d) : "l"(v));
    return d;
}
__device__ __forceinline__ void cp16(unsigned int sdst, const void* gsrc) {
    asm volatile("cp.async.cg.shared.global [%0], [%1], 16;"
                 :: "r"(sdst), "l"(gsrc));
}

__global__ __launch_bounds__(128, 7) void sphere_conv_kernel(
    const float* __restrict__ xr, const float* __restrict__ xi,
    const float* __restrict__ wr, const float* __restrict__ wi,
    float* __restrict__ out)
{
    __shared__ float4 w4s[C_ * F_];              // 4 KB: {wr,wr,wi,wi} per (f,c)
    __shared__ float  xs[STG_ * CPS_ * 2 * M_];  // 24 KB x ring

    const int tid = threadIdx.x;
    const int bl  = blockIdx.x;          // b*L + l
    const int b   = bl >> 8;             // L_ == 256
    const int l   = bl & (L_ - 1);

    // ---- interpolated weights into smem ----
    const float t = (float)(l * (N_ - 1)) * (1.0f / (float)(L_ - 1));
    int lo = (int)t;
    if (lo > N_ - 2) lo = N_ - 2;
    const float frac = t - (float)lo;
    const float om   = 1.0f - frac;
    for (int i = tid; i < F_ * C_; i += 128) {
        const int f = i & (F_ - 1);
        const int c = i >> 3;
        const int wix = (f * C_ + c) * N_ + lo;      // w layout (F,C,N,1)
        const float wrv = wr[wix] * om + wr[wix + 1] * frac;
        const float wiv = wi[wix] * om + wi[wix + 1] * frac;
        w4s[c * F_ + f] = make_float4(wrv, wrv, wiv, wiv);
    }

    const unsigned int sw = (unsigned int)__cvta_generic_to_shared(w4s);
    const unsigned int sx = (unsigned int)__cvta_generic_to_shared(xs);

    // ---- cp.async pipeline: thread t<64 loads xr rows, t>=64 loads xi rows ----
    const int th    = tid & 63;
    const char* gsrc = (const char*)(((tid < 64) ? xr : xi)
                       + (size_t)b * (C_ * CL_) + l * M_ + th * 4);
    const unsigned int xdst0 = sx + (tid < 64 ? 0u : 1024u) + (unsigned)(th * 16);

    // prologue: stage s lives in ring slot (s mod STG_); fill slots 0..STG_-2
#pragma unroll
    for (int s = 0; s < STG_ - 1; ++s) {
#pragma unroll
        for (int j = 0; j < CPS_; ++j)
            cp16(xdst0 + s * STGB_ + j * 2048,
                 gsrc + (size_t)(s * CPS_ + j) * (CL_ * 4));
        asm volatile("cp.async.commit_group;");
    }

    u64 pr[F_], pi[F_];
#pragma unroll
    for (int f = 0; f < F_; ++f) { pr[f] = 0ull; pi[f] = 0ull; }

    const unsigned int sxr = sx + (unsigned)(tid * 8);  // this thread's xr slot
    unsigned int xoff = 0;                               // read cursor (slot sg%3)
    unsigned int woff = (STG_ - 1) * STGB_;              // write cursor (slot (sg+2)%3)
    unsigned int soff = sw;                              // weight walk

#pragma unroll 1
    for (int sg = 0; sg < SG_; ++sg) {
        // For sg<SG_-1 the newest pending group is stage sg+1, so waiting for
        // "all but 1" guarantees stage sg is resident. On the LAST iteration
        // the only pending group IS the stage we consume -> full drain.
        if (sg == SG_ - 1) {
            asm volatile("cp.async.wait_group 0;");
        } else {
            asm volatile("cp.async.wait_group %0;" :: "n"(STG_ - 2));
        }
        __syncthreads();
#pragma unroll
        for (int j = 0; j < CPS_; ++j) {
            u64 x_r, x_i;
            asm("ld.shared.b64 %0, [%1];" : "=l"(x_r)
                : "r"(sxr + xoff + (unsigned)(j * 2048)));
            asm("ld.shared.b64 %0, [%1];" : "=l"(x_i)
                : "r"(sxr + xoff + (unsigned)(j * 2048 + 1024)));
            const u64 nxi = neg2(x_i);
#pragma unroll
            for (int f = 0; f < F_; ++f) {
                u64 wrr, wii;
                asm("ld.shared.v2.u64 {%0, %1}, [%2];"
                    : "=l"(wrr), "=l"(wii)
                    : "r"(soff + (unsigned)(f * 16)));
                pr[f] = ffma2(wrr, x_r, pr[f]);   // + wr*xr
                pr[f] = ffma2(wii, nxi, pr[f]);   // - wi*xi
                pi[f] = ffma2(wii, x_r, pi[f]);   // + wi*xr
                pi[f] = ffma2(wrr, x_i, pi[f]);   // + wr*xi
            }
            soff += F_ * 16;
        }
        __syncthreads();          // everyone done reading slot sg%3
        if (sg < SG_ - (STG_ - 1)) {
            const int s = sg + STG_ - 1;         // stage to prefetch
            // stage s -> slot (s mod STG_) == woff; consumed at sg-1, free.
#pragma unroll
            for (int j = 0; j < CPS_; ++j)
                cp16(xdst0 + woff + j * 2048,
                     gsrc + (size_t)(s * CPS_ + j) * (CL_ * 4));
            asm volatile("cp.async.commit_group;");
        }
        xoff += STGB_; if (xoff == STG_ * STGB_) xoff = 0;
        woff += STGB_; if (woff == STG_ * STGB_) woff = 0;
    }

    // ---- epilogue: scale = sqrt(1+l)/C, relu on real only ----
    const float s  = sqrtf(1.0f + (float)l) * (1.0f / (float)C_);
    float2* outp   = (float2*)out;
    const int ob   = (b * F_ * L_ + l) * M_ + 2 * tid;
#pragma unroll
    for (int f = 0; f < F_; ++f) {
        float r0, r1, i0, i1;
        upk(pr[f], r0, r1);
        upk(pi[f], i0, i1);
        const int idx = ob + f * (L_ * M_);
        outp[idx >> 1] = make_float2(fmaxf(r0 * s, 0.0f), fmaxf(r1 * s, 0.0f));
        outp[(idx + B_ * F_ * L_ * M_) >> 1] = make_float2(i0 * s, i1 * s);
    }
}

extern "C" void kernel_launch(void* const* d_in, const int* in_sizes, int n_in,
                              void* d_out, int out_size) {
    (void)in_sizes; (void)n_in; (void)out_size;
    sphere_conv_kernel<<<B_ * L_, 128>>>(
        (const float*)d_in[0], (const float*)d_in[1],
        (const float*)d_in[2], (const float*)d_in[3],
        (float*)d_out);
}